// round 14
// baseline (speedup 1.0000x reference)
#include <cuda_runtime.h>
#include <cuda_fp16.h>

#define EMB   1024
#define HEADS 16
#define HDIM  64
#define SEQ   2048
#define BATCH 4
#define MTOT  (BATCH * SEQ)   // 8192

// ---------------------------------------------------------------------------
// Scratch (fp16 everywhere between kernels)
// ---------------------------------------------------------------------------
__device__ __half g_hx[(size_t)MTOT * EMB];                    // x in fp16
__device__ __half g_hwq[(size_t)EMB * EMB];                    // Wq * (log2e/32)
__device__ __half g_hwk[(size_t)EMB * EMB];
__device__ __half g_hwv[(size_t)EMB * EMB];
__device__ __half g_hwo[(size_t)EMB * EMB];
__device__ __half g_qh[(size_t)BATCH * HEADS * SEQ * HDIM];    // [B,H,S,Dh]
__device__ __half g_kh[(size_t)BATCH * HEADS * SEQ * HDIM];
__device__ __half g_vh[(size_t)BATCH * HEADS * SEQ * HDIM];
__device__ __half g_oh[(size_t)MTOT * EMB];                    // attn out fp16

// ---------------------------------------------------------------------------
// Helpers
// ---------------------------------------------------------------------------
__device__ __forceinline__ unsigned pack_h2(float lo, float hi) {
    __half2 h = __floats2half2_rn(lo, hi);
    return *reinterpret_cast<unsigned*>(&h);
}
__device__ __forceinline__ unsigned h2exp2(unsigned x) {
    unsigned r;
    asm("ex2.approx.f16x2 %0, %1;" : "=r"(r) : "r"(x));
    return r;
}

__device__ __forceinline__ void cpa16(const void* smem, const void* gmem) {
    unsigned a = (unsigned)__cvta_generic_to_shared(smem);
    asm volatile("cp.async.cg.shared.global [%0],[%1],16;\n" :: "r"(a), "l"(gmem));
}
#define CP_COMMIT() asm volatile("cp.async.commit_group;\n")
#define CP_WAIT(N)  asm volatile("cp.async.wait_group %0;\n" :: "n"(N))

__device__ __forceinline__ void ldsm4(unsigned& r0, unsigned& r1, unsigned& r2,
                                      unsigned& r3, const void* p) {
    unsigned addr = (unsigned)__cvta_generic_to_shared(p);
    asm volatile("ldmatrix.sync.aligned.m8n8.x4.shared.b16 {%0,%1,%2,%3},[%4];"
                 : "=r"(r0), "=r"(r1), "=r"(r2), "=r"(r3) : "r"(addr));
}
__device__ __forceinline__ void ldsm4t(unsigned& r0, unsigned& r1, unsigned& r2,
                                       unsigned& r3, const void* p) {
    unsigned addr = (unsigned)__cvta_generic_to_shared(p);
    asm volatile("ldmatrix.sync.aligned.m8n8.x4.trans.shared.b16 {%0,%1,%2,%3},[%4];"
                 : "=r"(r0), "=r"(r1), "=r"(r2), "=r"(r3) : "r"(addr));
}
// fp32-accum mma
__device__ __forceinline__ void mma16816(float* d, const unsigned* a, const unsigned* b) {
    asm volatile(
        "mma.sync.aligned.m16n8k16.row.col.f32.f16.f16.f32 "
        "{%0,%1,%2,%3}, {%4,%5,%6,%7}, {%8,%9}, {%0,%1,%2,%3};\n"
        : "+f"(d[0]), "+f"(d[1]), "+f"(d[2]), "+f"(d[3])
        : "r"(a[0]), "r"(a[1]), "r"(a[2]), "r"(a[3]), "r"(b[0]), "r"(b[1]));
}
// fp16-accum mma
__device__ __forceinline__ void mma16816h(unsigned* d, const unsigned* a, const unsigned* b) {
    asm volatile(
        "mma.sync.aligned.m16n8k16.row.col.f16.f16.f16.f16 "
        "{%0,%1}, {%2,%3,%4,%5}, {%6,%7}, {%0,%1};\n"
        : "+r"(d[0]), "+r"(d[1])
        : "r"(a[0]), "r"(a[1]), "r"(a[2]), "r"(a[3]), "r"(b[0]), "r"(b[1]));
}

// Swizzled smem half-index for a 16B chunk: 128B rows, 8 chunks/row.
__device__ __forceinline__ int swz(int row, int c) {
    return (row * 8 + (c ^ (row & 7))) * 8;   // in halves
}

// ---------------------------------------------------------------------------
// Fused fp32 -> fp16 conversion: x, Wq(scaled), Wk, Wv, Wo in one launch.
// ---------------------------------------------------------------------------
#define NX4 (MTOT * EMB / 4)      // 2097152
#define NW4 (EMB * EMB / 4)       // 262144

__global__ void cvt_all(const float* __restrict__ x,
                        const float* __restrict__ Wq, const float* __restrict__ Wk,
                        const float* __restrict__ Wv, const float* __restrict__ Wo,
                        __half* __restrict__ hx,
                        __half* __restrict__ hwq, __half* __restrict__ hwk,
                        __half* __restrict__ hwv, __half* __restrict__ hwo,
                        float qscale)
{
    int i = blockIdx.x * blockDim.x + threadIdx.x;
    const float* s;
    __half* d;
    float scale = 1.0f;
    if (i < NX4) {
        s = x; d = hx;
    } else if (i < NX4 + NW4) {
        i -= NX4;            s = Wq; d = hwq; scale = qscale;
    } else if (i < NX4 + 2 * NW4) {
        i -= NX4 + NW4;      s = Wk; d = hwk;
    } else if (i < NX4 + 3 * NW4) {
        i -= NX4 + 2 * NW4;  s = Wv; d = hwv;
    } else {
        i -= NX4 + 3 * NW4;  s = Wo; d = hwo;
    }
    float4 f = ((const float4*)s)[i];
    uint2 p;
    p.x = pack_h2(f.x * scale, f.y * scale);
    p.y = pack_h2(f.z * scale, f.w * scale);
    ((uint2*)d)[i] = p;
}

// ---------------------------------------------------------------------------
// HGEMM: C = A(MxK) * B(NxK)^T + bias*bs
// fp16-accumulate within each K=64 stage (4 mma), promote to fp32 per stage.
// MODE 0: C fp32 [m*N+n].  MODE 1: C fp16 head-split [B,H,S,Dh].
// CTA tile 64x128, 128 threads (4 warps 1Mx4N, warp 64x32), 2-stage cp.async,
// single sync per stage. Smem 48KB; __launch_bounds__(128,4) -> 4 CTAs/SM.
// ---------------------------------------------------------------------------
template <int MODE>
__global__ __launch_bounds__(128, 4)
void hgemm(const __half* __restrict__ A,
           const __half* __restrict__ B0, const __half* __restrict__ B1,
           const __half* __restrict__ B2,
           const float* __restrict__ bi0, const float* __restrict__ bi1,
           const float* __restrict__ bi2, float bs0, float bs1, float bs2,
           void* C0v, void* C1v, void* C2v, int M, int N, int K)
{
    extern __shared__ __half dynsm[];
    const int z = blockIdx.z;
    const __half* B    = (z == 0) ? B0  : (z == 1) ? B1  : B2;
    const float*  bias = (z == 0) ? bi0 : (z == 1) ? bi1 : bi2;
    const float   bs   = (z == 0) ? bs0 : (z == 1) ? bs1 : bs2;
    void* Cv           = (z == 0) ? C0v : (z == 1) ? C1v : C2v;

    const int tid  = threadIdx.x;
    const int warp = tid >> 5;        // 0..3
    const int lane = tid & 31;
    const int g = lane >> 2;
    const int q = lane & 3;
    const int wn = warp * 32;
    const int bm = blockIdx.y * 64;
    const int bn = blockIdx.x * 128;

    const int arow = (lane & 7) + ((lane >> 3) & 1) * 8;
    const int acol = (lane >> 4) * 8;
    const int brow = ((lane >> 4) << 3) + (lane & 7);
    const int bcol = ((lane >> 3) & 1) << 3;

    const __half* Ag = A + (size_t)bm * K;
    const __half* Bg = B + (size_t)bn * K;

    const int srow = tid >> 3;        // 0..15 per pass
    const int sch  = tid & 7;

    float c[4][4][4];
#pragma unroll
    for (int mt = 0; mt < 4; mt++)
#pragma unroll
        for (int nt = 0; nt < 4; nt++)
#pragma unroll
            for (int i = 0; i < 4; i++) c[mt][nt][i] = 0.f;

    const int NIT = K >> 6;   // 16

    // Prefetch stage 0
    {
        __half* sA = dynsm;
        __half* sB = dynsm + 4096;
#pragma unroll
        for (int i = 0; i < 4; i++) {
            const int row = srow + i * 16;
            cpa16(&sA[swz(row, sch)], Ag + (size_t)row * K + sch * 8);
        }
#pragma unroll
        for (int i = 0; i < 8; i++) {
            const int row = srow + i * 16;
            cpa16(&sB[swz(row, sch)], Bg + (size_t)row * K + sch * 8);
        }
        CP_COMMIT();
    }

    for (int it = 0; it < NIT; it++) {
        CP_WAIT(0);            // stage it resident
        __syncthreads();       // all warps done with stage it-1's buffer

        if (it + 1 < NIT) {    // prefetch stage it+1 into (it+1)&1 (safe now)
            __half* sA = dynsm + ((it + 1) & 1) * 12288;
            __half* sB = sA + 4096;
            const int k0 = (it + 1) << 6;
#pragma unroll
            for (int i = 0; i < 4; i++) {
                const int row = srow + i * 16;
                cpa16(&sA[swz(row, sch)], Ag + (size_t)row * K + k0 + sch * 8);
            }
#pragma unroll
            for (int i = 0; i < 8; i++) {
                const int row = srow + i * 16;
                cpa16(&sB[swz(row, sch)], Bg + (size_t)row * K + k0 + sch * 8);
            }
            CP_COMMIT();
        }

        const __half* bA = dynsm + (it & 1) * 12288;
        const __half* bB = bA + 4096;

        // fp16 stage accumulators (zeroed each stage)
        unsigned hc[4][4][2];
#pragma unroll
        for (int mt = 0; mt < 4; mt++)
#pragma unroll
            for (int nt = 0; nt < 4; nt++) { hc[mt][nt][0] = 0u; hc[mt][nt][1] = 0u; }

#pragma unroll
        for (int ks = 0; ks < 4; ks++) {
            unsigned a[4][4], b[4][2];
#pragma unroll
            for (int mt = 0; mt < 4; mt++) {
                const int row = mt * 16 + arow;
                ldsm4(a[mt][0], a[mt][1], a[mt][2], a[mt][3],
                      &bA[swz(row, ks * 2 + (acol >> 3))]);
            }
#pragma unroll
            for (int jp = 0; jp < 2; jp++) {
                const int row = wn + jp * 16 + brow;
                unsigned r0, r1, r2, r3;
                ldsm4(r0, r1, r2, r3, &bB[swz(row, ks * 2 + (bcol >> 3))]);
                b[2 * jp][0] = r0; b[2 * jp][1] = r1;
                b[2 * jp + 1][0] = r2; b[2 * jp + 1][1] = r3;
            }
#pragma unroll
            for (int mt = 0; mt < 4; mt++)
#pragma unroll
                for (int nt = 0; nt < 4; nt++)
                    mma16816h(hc[mt][nt], a[mt], b[nt]);
        }

        // Promote stage partials to fp32
#pragma unroll
        for (int mt = 0; mt < 4; mt++)
#pragma unroll
            for (int nt = 0; nt < 4; nt++) {
                float2 f0 = __half22float2(*(__half2*)&hc[mt][nt][0]);
                float2 f1 = __half22float2(*(__half2*)&hc[mt][nt][1]);
                c[mt][nt][0] += f0.x; c[mt][nt][1] += f0.y;
                c[mt][nt][2] += f1.x; c[mt][nt][3] += f1.y;
            }
        // no trailing sync: next iteration's barrier provides it
    }

    // Epilogue
#pragma unroll
    for (int mt = 0; mt < 4; mt++) {
        const int r0 = bm + mt * 16 + g;
        const int r1 = r0 + 8;
#pragma unroll
        for (int nt = 0; nt < 4; nt++) {
            const int n0 = bn + wn + nt * 8 + 2 * q;
            const float b0f = bias[n0] * bs;
            const float b1f = bias[n0 + 1] * bs;
            if (MODE == 0) {
                float* C = (float*)Cv;
                *(float2*)&C[(size_t)r0 * N + n0] =
                    make_float2(c[mt][nt][0] + b0f, c[mt][nt][1] + b1f);
                *(float2*)&C[(size_t)r1 * N + n0] =
                    make_float2(c[mt][nt][2] + b0f, c[mt][nt][3] + b1f);
            } else {
                __half* C = (__half*)Cv;
                const int h = n0 >> 6, d = n0 & 63;
                const int bb0 = r0 >> 11, s0 = r0 & 2047;
                const int bb1 = r1 >> 11, s1 = r1 & 2047;
                *(unsigned*)&C[(((size_t)(bb0 * HEADS + h)) * SEQ + s0) * HDIM + d] =
                    pack_h2(c[mt][nt][0] + b0f, c[mt][nt][1] + b1f);
                *(unsigned*)&C[(((size_t)(bb1 * HEADS + h)) * SEQ + s1) * HDIM + d] =
                    pack_h2(c[mt][nt][2] + b0f, c[mt][nt][3] + b1f);
            }
        }
    }
}

// ---------------------------------------------------------------------------
// fp16 flash attention (round-13 version): fp16-accum QK^T + ex2.approx.f16x2
// + fp32-accum PV, single sync per K/V tile. 128 threads, 4 CTAs/SM.
// ---------------------------------------------------------------------------
__global__ __launch_bounds__(128, 4)
void attn_h(const __half* __restrict__ Q, const __half* __restrict__ K,
            const __half* __restrict__ V, __half* __restrict__ O)
{
    __shared__ __half Qs[64 * 64];
    __shared__ __half Ksm[2][64 * 64];
    __shared__ __half Vsm[2][64 * 64];

    const int bh   = blockIdx.y;
    const int q0   = blockIdx.x * 64;
    const int tid  = threadIdx.x;
    const int warp = tid >> 5;
    const int lane = tid & 31;
    const int g = lane >> 2;
    const int q = lane & 3;

    const __half* Qg = Q + ((size_t)bh * SEQ + q0) * HDIM;
    const __half* Kg = K + (size_t)bh * SEQ * HDIM;
    const __half* Vg = V + (size_t)bh * SEQ * HDIM;

    const int arow = (lane & 7) + ((lane >> 3) & 1) * 8;
    const int acol = (lane >> 4) * 8;
    const int brow = ((lane >> 4) << 3) + (lane & 7);
    const int bcol = ((lane >> 3) & 1) << 3;
    const int vrow = (lane & 7) + (((lane >> 3) & 1) << 3);
    const int vcol = (lane >> 4) << 3;

    const int srow = tid >> 3;     // 0..15 per pass
    const int sch  = tid & 7;

    // Prologue: Q + K/V tile 0
#pragma unroll
    for (int i = 0; i < 4; i++) {
        const int row = srow + i * 16;
        cpa16(&Qs[swz(row, sch)], Qg + row * HDIM + sch * 8);
    }
#pragma unroll
    for (int i = 0; i < 4; i++) {
        const int row = srow + i * 16;
        cpa16(&Ksm[0][swz(row, sch)], Kg + (size_t)row * HDIM + sch * 8);
        cpa16(&Vsm[0][swz(row, sch)], Vg + (size_t)row * HDIM + sch * 8);
    }
    CP_COMMIT();
    CP_WAIT(0);
    __syncthreads();

    unsigned qa[4][4];
#pragma unroll
    for (int ks = 0; ks < 4; ks++) {
        const int row = warp * 16 + arow;
        ldsm4(qa[ks][0], qa[ks][1], qa[ks][2], qa[ks][3],
              &Qs[swz(row, ks * 2 + (acol >> 3))]);
    }

    float o[8][4];
#pragma unroll
    for (int nt = 0; nt < 8; nt++)
#pragma unroll
        for (int i = 0; i < 4; i++) o[nt][i] = 0.f;
    float l0 = 0.f, l1 = 0.f;

    const int NT = SEQ / 64;   // 32
    for (int it = 0; it < NT; it++) {
        if (it > 0) {
            CP_WAIT(0);        // K/V tile it resident
            __syncthreads();   // all warps done with tile it-1's buffer
        }
        if (it + 1 < NT) {     // prefetch tile it+1 into (it+1)&1 (safe now)
            const int nb = (it + 1) & 1;
            const size_t kt = (size_t)(it + 1) * 64;
#pragma unroll
            for (int i = 0; i < 4; i++) {
                const int row = srow + i * 16;
                cpa16(&Ksm[nb][swz(row, sch)], Kg + (kt + row) * HDIM + sch * 8);
                cpa16(&Vsm[nb][swz(row, sch)], Vg + (kt + row) * HDIM + sch * 8);
            }
            CP_COMMIT();
        }

        const __half* Kb = Ksm[it & 1];
        const __half* Vb = Vsm[it & 1];

        // ---- S = Q K^T, fp16 accumulate (log2 domain, |s| < ~1) ----
        unsigned sh[8][2];
#pragma unroll
        for (int nt = 0; nt < 8; nt++) { sh[nt][0] = 0u; sh[nt][1] = 0u; }
#pragma unroll
        for (int ks = 0; ks < 4; ks++) {
#pragma unroll
            for (int jp = 0; jp < 4; jp++) {
                const int row = jp * 16 + brow;
                unsigned r0, r1, r2, r3;
                ldsm4(r0, r1, r2, r3, &Kb[swz(row, ks * 2 + (bcol >> 3))]);
                unsigned b0[2] = {r0, r1}, b1[2] = {r2, r3};
                mma16816h(sh[2 * jp], qa[ks], b0);
                mma16816h(sh[2 * jp + 1], qa[ks], b1);
            }
        }

        // ---- P = exp2(S) directly on C-frags (== PV A-frag layout) ----
#pragma unroll
        for (int nt = 0; nt < 8; nt++) {
            sh[nt][0] = h2exp2(sh[nt][0]);   // rows g
            sh[nt][1] = h2exp2(sh[nt][1]);   // rows g+8
            float2 f0 = __half22float2(*(__half2*)&sh[nt][0]);
            float2 f1 = __half22float2(*(__half2*)&sh[nt][1]);
            l0 += f0.x + f0.y;
            l1 += f1.x + f1.y;
        }

        // ---- O += P V, fp32 accumulate ----
#pragma unroll
        for (int kg = 0; kg < 4; kg++) {
            unsigned a[4] = {sh[2 * kg][0], sh[2 * kg][1],
                             sh[2 * kg + 1][0], sh[2 * kg + 1][1]};
#pragma unroll
            for (int dp = 0; dp < 4; dp++) {
                const int row = kg * 16 + vrow;
                unsigned r0, r1, r2, r3;
                ldsm4t(r0, r1, r2, r3, &Vb[swz(row, dp * 2 + (vcol >> 3))]);
                unsigned b0[2] = {r0, r1}, b1[2] = {r2, r3};
                mma16816(o[2 * dp], a, b0);
                mma16816(o[2 * dp + 1], a, b1);
            }
        }
        // no trailing sync: next iteration's barrier provides it
    }

    // ---- Final row-sum reduce (across quad lanes) + normalize ----
    l0 += __shfl_xor_sync(0xffffffffu, l0, 1);
    l0 += __shfl_xor_sync(0xffffffffu, l0, 2);
    l1 += __shfl_xor_sync(0xffffffffu, l1, 1);
    l1 += __shfl_xor_sync(0xffffffffu, l1, 2);
    const float inv0 = 1.0f / l0;
    const float inv1 = 1.0f / l1;
    const int b = bh >> 4;
    const int h = bh & 15;
    const int r0 = q0 + warp * 16 + g;
    const int r1 = r0 + 8;
#pragma unroll
    for (int nt = 0; nt < 8; nt++) {
        const int col = h * HDIM + nt * 8 + 2 * q;
        *(unsigned*)&O[((size_t)(b * SEQ + r0)) * EMB + col] =
            pack_h2(o[nt][0] * inv0, o[nt][1] * inv0);
        *(unsigned*)&O[((size_t)(b * SEQ + r1)) * EMB + col] =
            pack_h2(o[nt][2] * inv1, o[nt][3] * inv1);
    }
}

// ---------------------------------------------------------------------------
// Launch
// ---------------------------------------------------------------------------
extern "C" void kernel_launch(void* const* d_in, const int* in_sizes, int n_in,
                              void* d_out, int out_size)
{
    const float* x  = (const float*)d_in[0];
    const float* Wq = (const float*)d_in[1];
    const float* bq = (const float*)d_in[2];
    const float* Wk = (const float*)d_in[3];
    const float* bk = (const float*)d_in[4];
    const float* Wv = (const float*)d_in[5];
    const float* bv = (const float*)d_in[6];
    const float* Wo = (const float*)d_in[7];
    const float* bo = (const float*)d_in[8];
    float* out = (float*)d_out;

    __half *hx, *hwq, *hwk, *hwv, *hwo, *qh, *kh, *vh, *oh;
    cudaGetSymbolAddress((void**)&hx,  g_hx);
    cudaGetSymbolAddress((void**)&hwq, g_hwq);
    cudaGetSymbolAddress((void**)&hwk, g_hwk);
    cudaGetSymbolAddress((void**)&hwv, g_hwv);
    cudaGetSymbolAddress((void**)&hwo, g_hwo);
    cudaGetSymbolAddress((void**)&qh,  g_qh);
    cudaGetSymbolAddress((void**)&kh,  g_kh);
    cudaGetSymbolAddress((void**)&vh,  g_vh);
    cudaGetSymbolAddress((void**)&oh,  g_oh);

    const int GEMM_SMEM = 49152;   // 2 stages * (A 8KB + B 16KB)
    cudaFuncSetAttribute(hgemm<1>, cudaFuncAttributeMaxDynamicSharedMemorySize, GEMM_SMEM);
    cudaFuncSetAttribute(hgemm<0>, cudaFuncAttributeMaxDynamicSharedMemorySize, GEMM_SMEM);

    // log2(e)/sqrt(EMB): attention logits land directly in the exp2 domain
    const float qscale = 1.442695040888963f / 32.0f;

    const int total4 = NX4 + 4 * NW4;          // 3145728
    cvt_all<<<total4 / 256, 256>>>(x, Wq, Wk, Wv, Wo,
                                   hx, hwq, hwk, hwv, hwo, qscale);

    dim3 qkv_grid(EMB / 128, MTOT / 64, 3);    // (8, 128, 3)
    hgemm<1><<<qkv_grid, 128, GEMM_SMEM>>>(hx, hwq, hwk, hwv, bq, bk, bv,
                                           qscale, 1.0f, 1.0f,
                                           qh, kh, vh, MTOT, EMB, EMB);

    dim3 agrid(SEQ / 64, BATCH * HEADS);       // (32, 64)
    attn_h<<<agrid, 128>>>(qh, kh, vh, oh);

    dim3 ogrid(EMB / 128, MTOT / 64, 1);       // (8, 128)
    hgemm<0><<<ogrid, 128, GEMM_SMEM>>>(oh, hwo, hwo, hwo, bo, bo, bo,
                                        1.0f, 1.0f, 1.0f,
                                        out, out, out, MTOT, EMB, EMB);
}

// round 15
// speedup vs baseline: 1.1497x; 1.1497x over previous
#include <cuda_runtime.h>
#include <cuda_fp16.h>

#define EMB   1024
#define HEADS 16
#define HDIM  64
#define SEQ   2048
#define BATCH 4
#define MTOT  (BATCH * SEQ)   // 8192

// ---------------------------------------------------------------------------
// Scratch (fp16 everywhere between kernels)
// ---------------------------------------------------------------------------
__device__ __half g_hx[(size_t)MTOT * EMB];                    // x in fp16
__device__ __half g_hwq[(size_t)EMB * EMB];                    // Wq * (log2e/32)
__device__ __half g_hwk[(size_t)EMB * EMB];
__device__ __half g_hwv[(size_t)EMB * EMB];
__device__ __half g_hwo[(size_t)EMB * EMB];
__device__ __half g_qh[(size_t)BATCH * HEADS * SEQ * HDIM];    // [B,H,S,Dh]
__device__ __half g_kh[(size_t)BATCH * HEADS * SEQ * HDIM];
__device__ __half g_vh[(size_t)BATCH * HEADS * SEQ * HDIM];
__device__ __half g_oh[(size_t)MTOT * EMB];                    // attn out fp16

// ---------------------------------------------------------------------------
// Helpers
// ---------------------------------------------------------------------------
__device__ __forceinline__ unsigned pack_h2(float lo, float hi) {
    __half2 h = __floats2half2_rn(lo, hi);
    return *reinterpret_cast<unsigned*>(&h);
}
__device__ __forceinline__ unsigned h2exp2(unsigned x) {
    unsigned r;
    asm("ex2.approx.f16x2 %0, %1;" : "=r"(r) : "r"(x));
    return r;
}

__device__ __forceinline__ void cpa16(const void* smem, const void* gmem) {
    unsigned a = (unsigned)__cvta_generic_to_shared(smem);
    asm volatile("cp.async.cg.shared.global [%0],[%1],16;\n" :: "r"(a), "l"(gmem));
}
#define CP_COMMIT() asm volatile("cp.async.commit_group;\n")
#define CP_WAIT(N)  asm volatile("cp.async.wait_group %0;\n" :: "n"(N))

__device__ __forceinline__ void ldsm4(unsigned& r0, unsigned& r1, unsigned& r2,
                                      unsigned& r3, const void* p) {
    unsigned addr = (unsigned)__cvta_generic_to_shared(p);
    asm volatile("ldmatrix.sync.aligned.m8n8.x4.shared.b16 {%0,%1,%2,%3},[%4];"
                 : "=r"(r0), "=r"(r1), "=r"(r2), "=r"(r3) : "r"(addr));
}
__device__ __forceinline__ void ldsm4t(unsigned& r0, unsigned& r1, unsigned& r2,
                                       unsigned& r3, const void* p) {
    unsigned addr = (unsigned)__cvta_generic_to_shared(p);
    asm volatile("ldmatrix.sync.aligned.m8n8.x4.trans.shared.b16 {%0,%1,%2,%3},[%4];"
                 : "=r"(r0), "=r"(r1), "=r"(r2), "=r"(r3) : "r"(addr));
}
// fp32-accum mma
__device__ __forceinline__ void mma16816(float* d, const unsigned* a, const unsigned* b) {
    asm volatile(
        "mma.sync.aligned.m16n8k16.row.col.f32.f16.f16.f32 "
        "{%0,%1,%2,%3}, {%4,%5,%6,%7}, {%8,%9}, {%0,%1,%2,%3};\n"
        : "+f"(d[0]), "+f"(d[1]), "+f"(d[2]), "+f"(d[3])
        : "r"(a[0]), "r"(a[1]), "r"(a[2]), "r"(a[3]), "r"(b[0]), "r"(b[1]));
}
// fp16-accum mma (attention QK^T)
__device__ __forceinline__ void mma16816h(unsigned* d, const unsigned* a, const unsigned* b) {
    asm volatile(
        "mma.sync.aligned.m16n8k16.row.col.f16.f16.f16.f16 "
        "{%0,%1}, {%2,%3,%4,%5}, {%6,%7}, {%0,%1};\n"
        : "+r"(d[0]), "+r"(d[1])
        : "r"(a[0]), "r"(a[1]), "r"(a[2]), "r"(a[3]), "r"(b[0]), "r"(b[1]));
}

// Swizzled smem half-index for a 16B chunk: 128B rows, 8 chunks/row.
__device__ __forceinline__ int swz(int row, int c) {
    return (row * 8 + (c ^ (row & 7))) * 8;   // in halves
}

// ---------------------------------------------------------------------------
// Fused fp32 -> fp16 conversion: x, Wq(scaled), Wk, Wv, Wo in one launch.
// ---------------------------------------------------------------------------
#define NX4 (MTOT * EMB / 4)      // 2097152
#define NW4 (EMB * EMB / 4)       // 262144

__global__ void cvt_all(const float* __restrict__ x,
                        const float* __restrict__ Wq, const float* __restrict__ Wk,
                        const float* __restrict__ Wv, const float* __restrict__ Wo,
                        __half* __restrict__ hx,
                        __half* __restrict__ hwq, __half* __restrict__ hwk,
                        __half* __restrict__ hwv, __half* __restrict__ hwo,
                        float qscale)
{
    int i = blockIdx.x * blockDim.x + threadIdx.x;
    const float* s;
    __half* d;
    float scale = 1.0f;
    if (i < NX4) {
        s = x; d = hx;
    } else if (i < NX4 + NW4) {
        i -= NX4;            s = Wq; d = hwq; scale = qscale;
    } else if (i < NX4 + 2 * NW4) {
        i -= NX4 + NW4;      s = Wk; d = hwk;
    } else if (i < NX4 + 3 * NW4) {
        i -= NX4 + 2 * NW4;  s = Wv; d = hwv;
    } else {
        i -= NX4 + 3 * NW4;  s = Wo; d = hwo;
    }
    float4 f = ((const float4*)s)[i];
    uint2 p;
    p.x = pack_h2(f.x * scale, f.y * scale);
    p.y = pack_h2(f.z * scale, f.w * scale);
    ((uint2*)d)[i] = p;
}

// ---------------------------------------------------------------------------
// HGEMM (round-13 proven): C = A(MxK) * B(NxK)^T + bias*bs  (fp32 accum)
// MODE 0: C fp32 [m*N+n].  MODE 1: C fp16 head-split [B,H,S,Dh].
// CTA tile 64x128, BK=64, 128 threads (4 warps 1Mx4N, warp 64x32).
// 2-stage cp.async, single sync per stage. Smem 48KB -> 4 CTAs/SM.
// ---------------------------------------------------------------------------
template <int MODE>
__global__ __launch_bounds__(128)
void hgemm(const __half* __restrict__ A,
           const __half* __restrict__ B0, const __half* __restrict__ B1,
           const __half* __restrict__ B2,
           const float* __restrict__ bi0, const float* __restrict__ bi1,
           const float* __restrict__ bi2, float bs0, float bs1, float bs2,
           void* C0v, void* C1v, void* C2v, int M, int N, int K)
{
    extern __shared__ __half dynsm[];
    const int z = blockIdx.z;
    const __half* B    = (z == 0) ? B0  : (z == 1) ? B1  : B2;
    const float*  bias = (z == 0) ? bi0 : (z == 1) ? bi1 : bi2;
    const float   bs   = (z == 0) ? bs0 : (z == 1) ? bs1 : bs2;
    void* Cv           = (z == 0) ? C0v : (z == 1) ? C1v : C2v;

    const int tid  = threadIdx.x;
    const int warp = tid >> 5;        // 0..3
    const int lane = tid & 31;
    const int g = lane >> 2;
    const int q = lane & 3;
    const int wn = warp * 32;
    const int bm = blockIdx.y * 64;
    const int bn = blockIdx.x * 128;

    const int arow = (lane & 7) + ((lane >> 3) & 1) * 8;
    const int acol = (lane >> 4) * 8;
    const int brow = ((lane >> 4) << 3) + (lane & 7);
    const int bcol = ((lane >> 3) & 1) << 3;

    const __half* Ag = A + (size_t)bm * K;
    const __half* Bg = B + (size_t)bn * K;

    const int srow = tid >> 3;        // 0..15 per pass
    const int sch  = tid & 7;

    float c[4][4][4];
#pragma unroll
    for (int mt = 0; mt < 4; mt++)
#pragma unroll
        for (int nt = 0; nt < 4; nt++)
#pragma unroll
            for (int i = 0; i < 4; i++) c[mt][nt][i] = 0.f;

    const int NIT = K >> 6;   // 16

    // Prefetch stage 0
    {
        __half* sA = dynsm;
        __half* sB = dynsm + 4096;
#pragma unroll
        for (int i = 0; i < 4; i++) {
            const int row = srow + i * 16;
            cpa16(&sA[swz(row, sch)], Ag + (size_t)row * K + sch * 8);
        }
#pragma unroll
        for (int i = 0; i < 8; i++) {
            const int row = srow + i * 16;
            cpa16(&sB[swz(row, sch)], Bg + (size_t)row * K + sch * 8);
        }
        CP_COMMIT();
    }

    for (int it = 0; it < NIT; it++) {
        CP_WAIT(0);            // stage it resident
        __syncthreads();       // all warps done with stage it-1's buffer

        if (it + 1 < NIT) {    // prefetch stage it+1 into (it+1)&1 (safe now)
            __half* sA = dynsm + ((it + 1) & 1) * 12288;
            __half* sB = sA + 4096;
            const int k0 = (it + 1) << 6;
#pragma unroll
            for (int i = 0; i < 4; i++) {
                const int row = srow + i * 16;
                cpa16(&sA[swz(row, sch)], Ag + (size_t)row * K + k0 + sch * 8);
            }
#pragma unroll
            for (int i = 0; i < 8; i++) {
                const int row = srow + i * 16;
                cpa16(&sB[swz(row, sch)], Bg + (size_t)row * K + k0 + sch * 8);
            }
            CP_COMMIT();
        }

        const __half* bA = dynsm + (it & 1) * 12288;
        const __half* bB = bA + 4096;
#pragma unroll
        for (int ks = 0; ks < 4; ks++) {
            unsigned a[4][4], b[4][2];
#pragma unroll
            for (int mt = 0; mt < 4; mt++) {
                const int row = mt * 16 + arow;
                ldsm4(a[mt][0], a[mt][1], a[mt][2], a[mt][3],
                      &bA[swz(row, ks * 2 + (acol >> 3))]);
            }
#pragma unroll
            for (int jp = 0; jp < 2; jp++) {
                const int row = wn + jp * 16 + brow;
                unsigned r0, r1, r2, r3;
                ldsm4(r0, r1, r2, r3, &bB[swz(row, ks * 2 + (bcol >> 3))]);
                b[2 * jp][0] = r0; b[2 * jp][1] = r1;
                b[2 * jp + 1][0] = r2; b[2 * jp + 1][1] = r3;
            }
#pragma unroll
            for (int mt = 0; mt < 4; mt++)
#pragma unroll
                for (int nt = 0; nt < 4; nt++)
                    mma16816(c[mt][nt], a[mt], b[nt]);
        }
        // no trailing sync: next iteration's barrier provides it
    }

    // Epilogue
#pragma unroll
    for (int mt = 0; mt < 4; mt++) {
        const int r0 = bm + mt * 16 + g;
        const int r1 = r0 + 8;
#pragma unroll
        for (int nt = 0; nt < 4; nt++) {
            const int n0 = bn + wn + nt * 8 + 2 * q;
            const float b0f = bias[n0] * bs;
            const float b1f = bias[n0 + 1] * bs;
            if (MODE == 0) {
                float* C = (float*)Cv;
                *(float2*)&C[(size_t)r0 * N + n0] =
                    make_float2(c[mt][nt][0] + b0f, c[mt][nt][1] + b1f);
                *(float2*)&C[(size_t)r1 * N + n0] =
                    make_float2(c[mt][nt][2] + b0f, c[mt][nt][3] + b1f);
            } else {
                __half* C = (__half*)Cv;
                const int h = n0 >> 6, d = n0 & 63;
                const int bb0 = r0 >> 11, s0 = r0 & 2047;
                const int bb1 = r1 >> 11, s1 = r1 & 2047;
                *(unsigned*)&C[(((size_t)(bb0 * HEADS + h)) * SEQ + s0) * HDIM + d] =
                    pack_h2(c[mt][nt][0] + b0f, c[mt][nt][1] + b1f);
                *(unsigned*)&C[(((size_t)(bb1 * HEADS + h)) * SEQ + s1) * HDIM + d] =
                    pack_h2(c[mt][nt][2] + b0f, c[mt][nt][3] + b1f);
            }
        }
    }
}

// ---------------------------------------------------------------------------
// fp16 flash attention: fp16-accum QK^T + ex2.approx.f16x2 + fp32-accum PV.
// Softmax denominator via half2 tree reduction (one cvt per tile).
// Single sync per K/V tile. 128 threads, 4 CTAs/SM.
// ---------------------------------------------------------------------------
__global__ __launch_bounds__(128, 4)
void attn_h(const __half* __restrict__ Q, const __half* __restrict__ K,
            const __half* __restrict__ V, __half* __restrict__ O)
{
    __shared__ __half Qs[64 * 64];
    __shared__ __half Ksm[2][64 * 64];
    __shared__ __half Vsm[2][64 * 64];

    const int bh   = blockIdx.y;
    const int q0   = blockIdx.x * 64;
    const int tid  = threadIdx.x;
    const int warp = tid >> 5;
    const int lane = tid & 31;
    const int g = lane >> 2;
    const int q = lane & 3;

    const __half* Qg = Q + ((size_t)bh * SEQ + q0) * HDIM;
    const __half* Kg = K + (size_t)bh * SEQ * HDIM;
    const __half* Vg = V + (size_t)bh * SEQ * HDIM;

    const int arow = (lane & 7) + ((lane >> 3) & 1) * 8;
    const int acol = (lane >> 4) * 8;
    const int brow = ((lane >> 4) << 3) + (lane & 7);
    const int bcol = ((lane >> 3) & 1) << 3;
    const int vrow = (lane & 7) + (((lane >> 3) & 1) << 3);
    const int vcol = (lane >> 4) << 3;

    const int srow = tid >> 3;     // 0..15 per pass
    const int sch  = tid & 7;

    // Prologue: Q + K/V tile 0
#pragma unroll
    for (int i = 0; i < 4; i++) {
        const int row = srow + i * 16;
        cpa16(&Qs[swz(row, sch)], Qg + row * HDIM + sch * 8);
    }
#pragma unroll
    for (int i = 0; i < 4; i++) {
        const int row = srow + i * 16;
        cpa16(&Ksm[0][swz(row, sch)], Kg + (size_t)row * HDIM + sch * 8);
        cpa16(&Vsm[0][swz(row, sch)], Vg + (size_t)row * HDIM + sch * 8);
    }
    CP_COMMIT();
    CP_WAIT(0);
    __syncthreads();

    unsigned qa[4][4];
#pragma unroll
    for (int ks = 0; ks < 4; ks++) {
        const int row = warp * 16 + arow;
        ldsm4(qa[ks][0], qa[ks][1], qa[ks][2], qa[ks][3],
              &Qs[swz(row, ks * 2 + (acol >> 3))]);
    }

    float o[8][4];
#pragma unroll
    for (int nt = 0; nt < 8; nt++)
#pragma unroll
        for (int i = 0; i < 4; i++) o[nt][i] = 0.f;
    float l0 = 0.f, l1 = 0.f;

    const int NT = SEQ / 64;   // 32
    for (int it = 0; it < NT; it++) {
        if (it > 0) {
            CP_WAIT(0);        // K/V tile it resident
            __syncthreads();   // all warps done with tile it-1's buffer
        }
        if (it + 1 < NT) {     // prefetch tile it+1 into (it+1)&1 (safe now)
            const int nb = (it + 1) & 1;
            const size_t kt = (size_t)(it + 1) * 64;
#pragma unroll
            for (int i = 0; i < 4; i++) {
                const int row = srow + i * 16;
                cpa16(&Ksm[nb][swz(row, sch)], Kg + (kt + row) * HDIM + sch * 8);
                cpa16(&Vsm[nb][swz(row, sch)], Vg + (kt + row) * HDIM + sch * 8);
            }
            CP_COMMIT();
        }

        const __half* Kb = Ksm[it & 1];
        const __half* Vb = Vsm[it & 1];

        // ---- S = Q K^T, fp16 accumulate (log2 domain, |s| < ~1) ----
        unsigned sh[8][2];
#pragma unroll
        for (int nt = 0; nt < 8; nt++) { sh[nt][0] = 0u; sh[nt][1] = 0u; }
#pragma unroll
        for (int ks = 0; ks < 4; ks++) {
#pragma unroll
            for (int jp = 0; jp < 4; jp++) {
                const int row = jp * 16 + brow;
                unsigned r0, r1, r2, r3;
                ldsm4(r0, r1, r2, r3, &Kb[swz(row, ks * 2 + (bcol >> 3))]);
                unsigned b0[2] = {r0, r1}, b1[2] = {r2, r3};
                mma16816h(sh[2 * jp], qa[ks], b0);
                mma16816h(sh[2 * jp + 1], qa[ks], b1);
            }
        }

        // ---- P = exp2(S) directly on C-frags (== PV A-frag layout) ----
#pragma unroll
        for (int nt = 0; nt < 8; nt++) {
            sh[nt][0] = h2exp2(sh[nt][0]);   // rows g
            sh[nt][1] = h2exp2(sh[nt][1]);   // rows g+8
        }

        // ---- Denominator partials: half2 tree, one cvt per row-group ----
        {
            __half2 t0 = __hadd2(*(__half2*)&sh[0][0], *(__half2*)&sh[1][0]);
            __half2 t1 = __hadd2(*(__half2*)&sh[2][0], *(__half2*)&sh[3][0]);
            __half2 t2 = __hadd2(*(__half2*)&sh[4][0], *(__half2*)&sh[5][0]);
            __half2 t3 = __hadd2(*(__half2*)&sh[6][0], *(__half2*)&sh[7][0]);
            __half2 s01 = __hadd2(__hadd2(t0, t1), __hadd2(t2, t3));
            float2 f0 = __half22float2(s01);
            l0 += f0.x + f0.y;

            __half2 u0 = __hadd2(*(__half2*)&sh[0][1], *(__half2*)&sh[1][1]);
            __half2 u1 = __hadd2(*(__half2*)&sh[2][1], *(__half2*)&sh[3][1]);
            __half2 u2 = __hadd2(*(__half2*)&sh[4][1], *(__half2*)&sh[5][1]);
            __half2 u3 = __hadd2(*(__half2*)&sh[6][1], *(__half2*)&sh[7][1]);
            __half2 s23 = __hadd2(__hadd2(u0, u1), __hadd2(u2, u3));
            float2 f1 = __half22float2(s23);
            l1 += f1.x + f1.y;
        }

        // ---- O += P V, fp32 accumulate ----
#pragma unroll
        for (int kg = 0; kg < 4; kg++) {
            unsigned a[4] = {sh[2 * kg][0], sh[2 * kg][1],
                             sh[2 * kg + 1][0], sh[2 * kg + 1][1]};
#pragma unroll
            for (int dp = 0; dp < 4; dp++) {
                const int row = kg * 16 + vrow;
                unsigned r0, r1, r2, r3;
                ldsm4t(r0, r1, r2, r3, &Vb[swz(row, dp * 2 + (vcol >> 3))]);
                unsigned b0[2] = {r0, r1}, b1[2] = {r2, r3};
                mma16816(o[2 * dp], a, b0);
                mma16816(o[2 * dp + 1], a, b1);
            }
        }
        // no trailing sync: next iteration's barrier provides it
    }

    // ---- Final row-sum reduce (across quad lanes) + normalize ----
    l0 += __shfl_xor_sync(0xffffffffu, l0, 1);
    l0 += __shfl_xor_sync(0xffffffffu, l0, 2);
    l1 += __shfl_xor_sync(0xffffffffu, l1, 1);
    l1 += __shfl_xor_sync(0xffffffffu, l1, 2);
    const float inv0 = 1.0f / l0;
    const float inv1 = 1.0f / l1;
    const int b = bh >> 4;
    const int h = bh & 15;
    const int r0 = q0 + warp * 16 + g;
    const int r1 = r0 + 8;
#pragma unroll
    for (int nt = 0; nt < 8; nt++) {
        const int col = h * HDIM + nt * 8 + 2 * q;
        *(unsigned*)&O[((size_t)(b * SEQ + r0)) * EMB + col] =
            pack_h2(o[nt][0] * inv0, o[nt][1] * inv0);
        *(unsigned*)&O[((size_t)(b * SEQ + r1)) * EMB + col] =
            pack_h2(o[nt][2] * inv1, o[nt][3] * inv1);
    }
}

// ---------------------------------------------------------------------------
// Launch
// ---------------------------------------------------------------------------
extern "C" void kernel_launch(void* const* d_in, const int* in_sizes, int n_in,
                              void* d_out, int out_size)
{
    const float* x  = (const float*)d_in[0];
    const float* Wq = (const float*)d_in[1];
    const float* bq = (const float*)d_in[2];
    const float* Wk = (const float*)d_in[3];
    const float* bk = (const float*)d_in[4];
    const float* Wv = (const float*)d_in[5];
    const float* bv = (const float*)d_in[6];
    const float* Wo = (const float*)d_in[7];
    const float* bo = (const float*)d_in[8];
    float* out = (float*)d_out;

    __half *hx, *hwq, *hwk, *hwv, *hwo, *qh, *kh, *vh, *oh;
    cudaGetSymbolAddress((void**)&hx,  g_hx);
    cudaGetSymbolAddress((void**)&hwq, g_hwq);
    cudaGetSymbolAddress((void**)&hwk, g_hwk);
    cudaGetSymbolAddress((void**)&hwv, g_hwv);
    cudaGetSymbolAddress((void**)&hwo, g_hwo);
    cudaGetSymbolAddress((void**)&qh,  g_qh);
    cudaGetSymbolAddress((void**)&kh,  g_kh);
    cudaGetSymbolAddress((void**)&vh,  g_vh);
    cudaGetSymbolAddress((void**)&oh,  g_oh);

    const int GEMM_SMEM = 49152;   // 2 stages * (A 8KB + B 16KB)
    cudaFuncSetAttribute(hgemm<1>, cudaFuncAttributeMaxDynamicSharedMemorySize, GEMM_SMEM);
    cudaFuncSetAttribute(hgemm<0>, cudaFuncAttributeMaxDynamicSharedMemorySize, GEMM_SMEM);

    // log2(e)/sqrt(EMB): attention logits land directly in the exp2 domain
    const float qscale = 1.442695040888963f / 32.0f;

    const int total4 = NX4 + 4 * NW4;          // 3145728
    cvt_all<<<total4 / 256, 256>>>(x, Wq, Wk, Wv, Wo,
                                   hx, hwq, hwk, hwv, hwo, qscale);

    dim3 qkv_grid(EMB / 128, MTOT / 64, 3);    // (8, 128, 3)
    hgemm<1><<<qkv_grid, 128, GEMM_SMEM>>>(hx, hwq, hwk, hwv, bq, bk, bv,
                                           qscale, 1.0f, 1.0f,
                                           qh, kh, vh, MTOT, EMB, EMB);

    dim3 agrid(SEQ / 64, BATCH * HEADS);       // (32, 64)
    attn_h<<<agrid, 128>>>(qh, kh, vh, oh);

    dim3 ogrid(EMB / 128, MTOT / 64, 1);       // (8, 128)
    hgemm<0><<<ogrid, 128, GEMM_SMEM>>>(oh, hwo, hwo, hwo, bo, bo, bo,
                                        1.0f, 1.0f, 1.0f,
                                        out, out, out, MTOT, EMB, EMB);
}